// round 7
// baseline (speedup 1.0000x reference)
#include <cuda_runtime.h>

#define DT 0.01f

constexpr int B    = 2;
constexpr int N    = 20000;
constexpr int D    = 64;
constexpr int E    = 320000;
constexpr int ND4  = N * (D / 4);    // float4s per batch      = 320,000
constexpr int TOT4 = B * ND4;        // float4s per (B,N,D)    = 640,000
constexpr int CAP  = 128;            // max supported in-degree (Poisson(16) tail << CAP)

// Scratch (allocation-free rule: __device__ globals, zero-initialized at load).
__device__ int g_cursor[N];          // per-node in-degree / write cursor
__device__ int g_bucket[N * CAP];    // src lists grouped by dst

// ---------------------------------------------------------------------------
// K1: bucket edges by dst.  pos = cursor[dst]++ ; bucket[dst][pos] = src
// ---------------------------------------------------------------------------
__global__ void bucket_kernel(const int2* __restrict__ edges) {
    int e = blockIdx.x * blockDim.x + threadIdx.x;
    if (e >= E) return;
    int2 ed = __ldg(&edges[e]);
    int pos = atomicAdd(&g_cursor[ed.y], 1);
    if (pos < CAP) g_bucket[ed.y * CAP + pos] = ed.x;
}

// ---------------------------------------------------------------------------
// K2: one warp per node.  Lane split: half = lane>>4 selects batch,
// c = lane&15 selects the float4 chunk of D.  One LDG.128 per src per lane,
// staged through an explicit v[8] array so 8 loads are architecturally live
// (forces the register budget that enables MLP=8).  Fused symplectic +
// Kalman epilogue; resets cursor[n] for the next graph replay.
// ---------------------------------------------------------------------------
__global__ void node_kernel(
        const float* __restrict__ q, const float* __restrict__ p,
        const float* __restrict__ obs, const float* __restrict__ kg,
        float* __restrict__ out) {
    int n = blockIdx.x * (blockDim.x >> 5) + (threadIdx.x >> 5);
    if (n >= N) return;
    int lane = threadIdx.x & 31;
    int c    = lane & 15;        // float4 chunk within D
    int half = lane >> 4;        // batch index

    // Independent scoreboarded loads issued back-to-back.
    int my_src0 = g_bucket[n * CAP + lane];   // first 32 srcs (may include stale tail)
    int deg     = g_cursor[n];                // broadcast load
    if (lane == 0) g_cursor[n] = 0;           // reset for next replay (after read)

    const float4* q4 = reinterpret_cast<const float4*>(q);
    const float4* p4 = reinterpret_cast<const float4*>(p);
    int base4 = half * ND4 + c;               // loop-invariant address part

    float4 acc = make_float4(0.f, 0.f, 0.f, 0.f);

    int degc = min(deg, CAP);
    for (int chunk = 0; chunk * 32 < degc; chunk++) {
        int ms  = (chunk == 0) ? my_src0
                               : g_bucket[n * CAP + chunk * 32 + lane];
        int lim = min(degc - chunk * 32, 32);
        for (int b = 0; b < lim; b += 8) {
            float4 v[8];
            #pragma unroll
            for (int j = 0; j < 8; j++) {
                int src = __shfl_sync(0xffffffffu, ms, b + j);
                v[j] = __ldg(&q4[base4 + src * 16]);   // unconditional: stale srcs are valid indices
            }
            #pragma unroll
            for (int j = 0; j < 8; j++) {
                if (b + j < lim) {
                    acc.x += v[j].x;  acc.y += v[j].y;
                    acc.z += v[j].z;  acc.w += v[j].w;
                }
            }
        }
    }

    float dg  = (float)deg;
    int   idx = base4 + n * 16;          // this lane's element of (half, n, c)
    float4 qq = q4[idx];
    float4 pp = p4[idx];

    // msg = deg * q[n] - sum(q[src])
    float mx = dg * qq.x - acc.x;
    float my = dg * qq.y - acc.y;
    float mz = dg * qq.z - acc.z;
    float mw = dg * qq.w - acc.w;

    // p_half = p + 0.5*DT*msg ; q_new = q + DT*p_half ; p_new = p + DT*msg
    float qnx = qq.x + DT * (pp.x + 0.5f * DT * mx);
    float qny = qq.y + DT * (pp.y + 0.5f * DT * my);
    float qnz = qq.z + DT * (pp.z + 0.5f * DT * mz);
    float qnw = qq.w + DT * (pp.w + 0.5f * DT * mw);

    float pnx = pp.x + DT * mx;
    float pny = pp.y + DT * my;
    float pnz = pp.z + DT * mz;
    float pnw = pp.w + DT * mw;

    if (n == 0) {
        const float4* obs4 = reinterpret_cast<const float4*>(obs);
        const float4* kg4  = reinterpret_cast<const float4*>(kg);
        float4 ob = obs4[half * 16 + c];   // observations[half]
        float4 kq = kg4[c];                // kalman_gain[0:D]
        float4 kp = kg4[16 + c];           // kalman_gain[D:2D]

        float ix = ob.x - qnx, iy = ob.y - qny, iz = ob.z - qnz, iw = ob.w - qnw;
        qnx += kq.x * ix;  qny += kq.y * iy;  qnz += kq.z * iz;  qnw += kq.w * iw;
        pnx += kp.x * ix;  pny += kp.y * iy;  pnz += kp.z * iz;  pnw += kp.w * iw;
    }

    float4* o4 = reinterpret_cast<float4*>(out);
    o4[idx]        = make_float4(qnx, qny, qnz, qnw);   // q_new
    o4[TOT4 + idx] = make_float4(pnx, pny, pnz, pnw);   // p_new
}

extern "C" void kernel_launch(void* const* d_in, const int* in_sizes, int n_in,
                              void* d_out, int out_size) {
    const float* q   = (const float*)d_in[0];   // node_q  (B,N,D) f32
    const float* p   = (const float*)d_in[1];   // node_p  (B,N,D) f32
    const float* obs = (const float*)d_in[2];   // observations (B,D) f32
    const float* kg  = (const float*)d_in[3];   // kalman_gain (2D,) f32
    const int2*  edg = (const int2*)d_in[4];    // edges (E,2) i32
    float* out = (float*)d_out;

    bucket_kernel<<<(E + 255) / 256, 256>>>(edg);
    node_kernel<<<(N * 32 + 255) / 256, 256>>>(q, p, obs, kg, out);
}